// round 1
// baseline (speedup 1.0000x reference)
#include <cuda_runtime.h>
#include <math.h>

// ---------------------------------------------------------------------------
// Shapes (all fixed by the problem):
//  x:      (16, 3, 16, 128, 128)
//  h1:     (16, 4,  8,  64,  64)   conv k4 s2 p1 + relu
//  h2:     (16, 8,  4,  32,  32)   conv k4 s2 p1 + relu
//  z:      (16,16,  4,  32,  32)   conv k3 s1 p1 + clip[0,6]
//  quant:  (16,16,  4,  32,  32)
//  d1:     (16, 8,  8,  64,  64)   deconv k4 s2 p1 + relu
//  d2:     (16, 4, 16, 128, 128)   deconv k4 s2 p1 + relu
//  out:    (16, 3, 16, 128, 128)   deconv k3 s1 p1
// ---------------------------------------------------------------------------

#define OUT_ELEMS (16*3*16*128*128)   // 12,582,912
#define NPOS      (16*4*32*32)        // 65,536 flattened spatial positions
#define ZC        16
#define NCODE     32

// scratch (device globals -- allocation-free rule)
__device__ float g_h1[16*4*8*64*64];
__device__ float g_h2[16*8*4*32*32];
__device__ float g_z [16*16*4*32*32];
__device__ float g_q [16*16*4*32*32];
__device__ float g_d1[16*8*8*64*64];
__device__ float g_d2[16*4*16*128*128];
__device__ float g_sqsum;
__device__ int   g_hist[NCODE];

__global__ void zero_acc_kernel() {
    int t = threadIdx.x;
    if (t == 0) g_sqsum = 0.f;
    if (t < NCODE) g_hist[t] = 0;
}

// ------------------------- direct conv3d ----------------------------------
// mode: 0 = linear, 1 = relu, 2 = clip[0,6]
__global__ void conv3d_kernel(const float* __restrict__ in,
                              const float* __restrict__ w,
                              const float* __restrict__ bias,
                              float* __restrict__ out,
                              int B, int Ci, int Di, int Hi, int Wi,
                              int Co, int Do, int Ho, int Wo,
                              int K, int S, int P, int mode)
{
    long long total = (long long)B * Co * Do * Ho * Wo;
    long long t = (long long)blockIdx.x * blockDim.x + threadIdx.x;
    if (t >= total) return;
    int wo = t % Wo; long long r = t / Wo;
    int ho = r % Ho; r /= Ho;
    int dd = r % Do; r /= Do;
    int co = r % Co; r /= Co;
    int n  = (int)r;

    float acc = __ldg(&bias[co]);
    int HW = Hi * Wi;
    for (int ci = 0; ci < Ci; ci++) {
        const float* inb = in + ((long long)(n * Ci + ci) * Di) * HW;
        const float* wb  = w + ((long long)(co * Ci + ci) * K) * K * K;
        for (int kd = 0; kd < K; kd++) {
            int id = dd * S - P + kd;
            if (id < 0 || id >= Di) continue;
            for (int kh = 0; kh < K; kh++) {
                int ih = ho * S - P + kh;
                if (ih < 0 || ih >= Hi) continue;
                const float* row = inb + (long long)id * HW + (long long)ih * Wi;
                const float* wr  = wb + (kd * K + kh) * K;
                for (int kw = 0; kw < K; kw++) {
                    int iw = wo * S - P + kw;
                    if (iw < 0 || iw >= Wi) continue;
                    acc += row[iw] * __ldg(&wr[kw]);
                }
            }
        }
    }
    if (mode == 1) acc = fmaxf(acc, 0.f);
    else if (mode == 2) acc = fminf(fmaxf(acc, 0.f), 6.f);
    out[t] = acc;
}

// --------------------- transposed conv3d (gather) --------------------------
// PyTorch ConvTranspose3d semantics: out[n,co,o] += in[n,ci,i] * w[ci,co,k],
// with o = i*S - P + k. Weight layout (Ci, Co, K, K, K).
__global__ void deconv3d_kernel(const float* __restrict__ in,
                                const float* __restrict__ w,
                                const float* __restrict__ bias,
                                float* __restrict__ out,
                                int B, int Ci, int Di, int Hi, int Wi,
                                int Co, int Do, int Ho, int Wo,
                                int K, int S, int P, int relu)
{
    long long total = (long long)B * Co * Do * Ho * Wo;
    long long t = (long long)blockIdx.x * blockDim.x + threadIdx.x;
    if (t >= total) return;
    int wo = t % Wo; long long r = t / Wo;
    int ho = r % Ho; r /= Ho;
    int dd = r % Do; r /= Do;
    int co = r % Co; r /= Co;
    int n  = (int)r;

    // valid (k, i) pairs per dimension
    int nd = 0, idd[4], kdd[4];
    int nh = 0, ihh[4], khh[4];
    int nw = 0, iww[4], kww[4];
    for (int k = 0; k < K; k++) {
        int q = dd + P - k;
        if (q >= 0 && q % S == 0 && q / S < Di) { idd[nd] = q / S; kdd[nd] = k; nd++; }
        q = ho + P - k;
        if (q >= 0 && q % S == 0 && q / S < Hi) { ihh[nh] = q / S; khh[nh] = k; nh++; }
        q = wo + P - k;
        if (q >= 0 && q % S == 0 && q / S < Wi) { iww[nw] = q / S; kww[nw] = k; nw++; }
    }

    float acc = __ldg(&bias[co]);
    int HW = Hi * Wi;
    for (int ci = 0; ci < Ci; ci++) {
        const float* inb = in + ((long long)(n * Ci + ci) * Di) * HW;
        const float* wb  = w + ((long long)(ci * Co + co) * K) * K * K;
        for (int a = 0; a < nd; a++) {
            const float* ind = inb + (long long)idd[a] * HW;
            const float* wd  = wb + kdd[a] * K * K;
            for (int bI = 0; bI < nh; bI++) {
                const float* row = ind + (long long)ihh[bI] * Wi;
                const float* wr  = wd + khh[bI] * K;
                for (int c = 0; c < nw; c++) {
                    acc += row[iww[c]] * __ldg(&wr[kww[c]]);
                }
            }
        }
    }
    if (relu) acc = fmaxf(acc, 0.f);
    out[t] = acc;
}

// ----------------------------- VQ kernel -----------------------------------
// one thread per flattened spatial position (B*D*H*W = 65536)
__global__ void vq_kernel(const float* __restrict__ z,
                          const float* __restrict__ emb_in,
                          float* __restrict__ quant,
                          float* __restrict__ codes_out)
{
    __shared__ float se[NCODE * ZC];
    __shared__ float sn[NCODE];
    __shared__ int   sh[NCODE];
    int tid = threadIdx.x;

    for (int i = tid; i < NCODE * ZC; i += blockDim.x) {
        int row = i / ZC;
        float v = __ldg(&emb_in[i]);
        if (row == 0) v = 0.f;
        if (row == 1) v = 6.f;
        se[i] = v;
    }
    if (tid < NCODE) sh[tid] = 0;
    __syncthreads();
    if (tid < NCODE) {
        float s = 0.f;
        for (int c = 0; c < ZC; c++) { float v = se[tid * ZC + c]; s += v * v; }
        sn[tid] = s;
    }
    __syncthreads();

    int p = blockIdx.x * blockDim.x + tid;   // 0..65535
    int b = p >> 12;           // / (4*32*32)
    int s = p & 4095;
    const float* zb = z + (long long)(b * ZC) * 4096 + s;

    float f[ZC];
    float fn = 0.f;
    #pragma unroll
    for (int c = 0; c < ZC; c++) { f[c] = zb[(long long)c * 4096]; fn += f[c] * f[c]; }

    int best = 0; float bestd = INFINITY;
    for (int e = 0; e < NCODE; e++) {
        float dot = 0.f;
        #pragma unroll
        for (int c = 0; c < ZC; c++) dot += f[c] * se[e * ZC + c];
        float d = fn - 2.f * dot + sn[e];
        if (d < bestd) { bestd = d; best = e; }   // strict < keeps first index on ties
    }

    codes_out[p] = (float)best;
    float* qb = quant + (long long)(b * ZC) * 4096 + s;
    float diff2 = 0.f;
    #pragma unroll
    for (int c = 0; c < ZC; c++) {
        float e = se[best * ZC + c];
        qb[(long long)c * 4096] = e;
        float d = e - f[c];
        diff2 += d * d;
    }

    atomicAdd(&sh[best], 1);
    // warp-reduce diff2, one global atomic per warp
    #pragma unroll
    for (int o = 16; o > 0; o >>= 1) diff2 += __shfl_down_sync(0xffffffff, diff2, o);
    if ((tid & 31) == 0) atomicAdd(&g_sqsum, diff2);
    __syncthreads();
    if (tid < NCODE) atomicAdd(&g_hist[tid], sh[tid]);
}

// --------------------------- finalize scalars ------------------------------
__global__ void finalize_kernel(const float* __restrict__ cluster_size,
                                float* __restrict__ out)
{
    if (threadIdx.x == 0 && blockIdx.x == 0) {
        float invN = 1.f / (float)NPOS;
        float ent = 0.f;
        int used = 0;
        for (int i = 0; i < NCODE; i++) {
            float p = (float)g_hist[i] * invN;
            ent += p * logf(p + 1e-10f);
            if (__ldg(&cluster_size[i]) > 1e-5f) used++;
        }
        out[OUT_ELEMS] = 0.25f * g_sqsum / (float)(NPOS * ZC);       // vq_loss
        out[OUT_ELEMS + 1 + NPOS] = expf(-ent);                      // perplexity
        out[OUT_ELEMS + 2 + NPOS] = (float)used / (float)NCODE;      // used_codes
    }
}

// ---------------------------------------------------------------------------
extern "C" void kernel_launch(void* const* d_in, const int* in_sizes, int n_in,
                              void* d_out, int out_size)
{
    const float* x       = (const float*)d_in[0];
    // d_in[1] = epoch (int, unused: epoch=60 >= 50 branch is compiled in)
    const float* enc_w1  = (const float*)d_in[2];
    const float* enc_b1  = (const float*)d_in[3];
    const float* enc_w2  = (const float*)d_in[4];
    const float* enc_b2  = (const float*)d_in[5];
    const float* enc_w4  = (const float*)d_in[6];
    const float* enc_b4  = (const float*)d_in[7];
    const float* dec_w1  = (const float*)d_in[8];
    const float* dec_b1  = (const float*)d_in[9];
    const float* dec_w3  = (const float*)d_in[10];
    const float* dec_b3  = (const float*)d_in[11];
    const float* dec_w4  = (const float*)d_in[12];
    const float* dec_b4  = (const float*)d_in[13];
    const float* emb     = (const float*)d_in[14];
    const float* clsz    = (const float*)d_in[15];
    float* out = (float*)d_out;

    float *h1, *h2, *z, *q, *d1, *d2;
    cudaGetSymbolAddress((void**)&h1, g_h1);
    cudaGetSymbolAddress((void**)&h2, g_h2);
    cudaGetSymbolAddress((void**)&z,  g_z);
    cudaGetSymbolAddress((void**)&q,  g_q);
    cudaGetSymbolAddress((void**)&d1, g_d1);
    cudaGetSymbolAddress((void**)&d2, g_d2);

    const int T = 256;

    zero_acc_kernel<<<1, 64>>>();

    // encoder
    {   // conv1: (16,3,16,128,128) -> (16,4,8,64,64), k4 s2 p1, relu
        long long n = 16LL*4*8*64*64;
        conv3d_kernel<<<(unsigned)((n + T - 1) / T), T>>>(x, enc_w1, enc_b1, h1,
            16, 3, 16, 128, 128, 4, 8, 64, 64, 4, 2, 1, 1);
    }
    {   // conv2: -> (16,8,4,32,32), k4 s2 p1, relu
        long long n = 16LL*8*4*32*32;
        conv3d_kernel<<<(unsigned)((n + T - 1) / T), T>>>(h1, enc_w2, enc_b2, h2,
            16, 4, 8, 64, 64, 8, 4, 32, 32, 4, 2, 1, 1);
    }
    {   // conv4: -> z (16,16,4,32,32), k3 s1 p1, clip[0,6]
        long long n = 16LL*16*4*32*32;
        conv3d_kernel<<<(unsigned)((n + T - 1) / T), T>>>(h2, enc_w4, enc_b4, z,
            16, 8, 4, 32, 32, 16, 4, 32, 32, 3, 1, 1, 2);
    }

    // VQ: codes written directly to out[OUT_ELEMS+1 ...]
    vq_kernel<<<NPOS / T, T>>>(z, emb, q, out + OUT_ELEMS + 1);
    finalize_kernel<<<1, 32>>>(clsz, out);

    // decoder (input = quant; quantized_st == quant numerically)
    {   // deconv1: (16,16,4,32,32) -> (16,8,8,64,64), k4 s2 p1, relu
        long long n = 16LL*8*8*64*64;
        deconv3d_kernel<<<(unsigned)((n + T - 1) / T), T>>>(q, dec_w1, dec_b1, d1,
            16, 16, 4, 32, 32, 8, 8, 64, 64, 4, 2, 1, 1);
    }
    {   // deconv3: -> (16,4,16,128,128), k4 s2 p1, relu
        long long n = 16LL*4*16*128*128;
        deconv3d_kernel<<<(unsigned)((n + T - 1) / T), T>>>(d1, dec_w3, dec_b3, d2,
            16, 8, 8, 64, 64, 4, 16, 128, 128, 4, 2, 1, 1);
    }
    {   // deconv4: -> out (16,3,16,128,128), k3 s1 p1, linear
        long long n = (long long)OUT_ELEMS;
        deconv3d_kernel<<<(unsigned)((n + T - 1) / T), T>>>(d2, dec_w4, dec_b4, out,
            16, 4, 16, 128, 128, 3, 16, 128, 128, 3, 1, 1, 0);
    }
}

// round 2
// speedup vs baseline: 12.2381x; 12.2381x over previous
#include <cuda_runtime.h>
#include <math.h>

// ---------------------------------------------------------------------------
//  x:      (16, 3, 16, 128, 128)
//  h1:     (16, 4,  8,  64,  64)   conv k4 s2 p1 + relu
//  h2:     (16, 8,  4,  32,  32)   conv k4 s2 p1 + relu
//  z:      (16,16,  4,  32,  32)   conv k3 s1 p1 + clip[0,6]
//  quant:  (16,16,  4,  32,  32)
//  d1:     (16, 8,  8,  64,  64)   deconv k4 s2 p1 + relu
//  d2:     (16, 4, 16, 128, 128)   deconv k4 s2 p1 + relu
//  out:    (16, 3, 16, 128, 128)   deconv k3 s1 p1
// ---------------------------------------------------------------------------

#define OUT_ELEMS (16*3*16*128*128)   // 12,582,912
#define NPOS      (16*4*32*32)        // 65,536
#define ZC        16
#define NCODE     32

__device__ float g_h1[16*4*8*64*64];
__device__ float g_h2[16*8*4*32*32];
__device__ float g_z [16*16*4*32*32];
__device__ float g_q [16*16*4*32*32];
__device__ float g_d1[16*8*8*64*64];
__device__ float g_d2[16*4*16*128*128];
__device__ float g_sqsum;
__device__ int   g_hist[NCODE];

__global__ void zero_acc_kernel() {
    int t = threadIdx.x;
    if (t == 0) g_sqsum = 0.f;
    if (t < NCODE) g_hist[t] = 0;
}

// ========================= conv1 =============================
// x (16,3,16,128,128) -> h1 (16,4,8,64,64), k4 s2 p1, relu
// thread: 4 consecutive wo, all 4 co. threads = 16*8*64*16 = 131072
__global__ __launch_bounds__(256) void conv1_kernel(
    const float* __restrict__ x, const float* __restrict__ w,
    const float* __restrict__ bias, float* __restrict__ out)
{
    __shared__ float sw[768];   // [ci3][kd4][kh4][kw4][co4]
    __shared__ float sb[4];
    for (int i = threadIdx.x; i < 768; i += blockDim.x) {
        int co = i & 3, kw = (i >> 2) & 3, kh = (i >> 4) & 3, kd = (i >> 6) & 3, ci = i >> 8;
        sw[i] = w[(((co*3+ci)*4+kd)*4+kh)*4+kw];
    }
    if (threadIdx.x < 4) sb[threadIdx.x] = bias[threadIdx.x];
    __syncthreads();

    int idx = blockIdx.x * blockDim.x + threadIdx.x;
    int wg = idx & 15;
    int h  = (idx >> 4) & 63;
    int d  = (idx >> 10) & 7;
    int b  = idx >> 13;

    float acc[4][4];
    #pragma unroll
    for (int co = 0; co < 4; co++)
        #pragma unroll
        for (int j = 0; j < 4; j++) acc[co][j] = sb[co];

    int iwb = 8*wg - 1;
    for (int ci = 0; ci < 3; ci++) {
        const float* inc = x + (long long)(b*3+ci) * 16 * 16384;
        #pragma unroll
        for (int kd = 0; kd < 4; kd++) {
            int id = 2*d - 1 + kd;
            if (id < 0 || id >= 16) continue;
            #pragma unroll
            for (int kh = 0; kh < 4; kh++) {
                int ih = 2*h - 1 + kh;
                if (ih < 0 || ih >= 128) continue;
                const float* row = inc + id*16384 + ih*128;
                float v[10];
                #pragma unroll
                for (int m = 0; m < 10; m++) {
                    int iw = iwb + m;
                    v[m] = (iw >= 0 && iw < 128) ? row[iw] : 0.f;
                }
                const float4* w4 = (const float4*)&sw[((ci*4+kd)*4+kh)*16];
                #pragma unroll
                for (int kw = 0; kw < 4; kw++) {
                    float4 wv = w4[kw];
                    #pragma unroll
                    for (int j = 0; j < 4; j++) {
                        float vv = v[2*j+kw];
                        acc[0][j] = fmaf(vv, wv.x, acc[0][j]);
                        acc[1][j] = fmaf(vv, wv.y, acc[1][j]);
                        acc[2][j] = fmaf(vv, wv.z, acc[2][j]);
                        acc[3][j] = fmaf(vv, wv.w, acc[3][j]);
                    }
                }
            }
        }
    }
    #pragma unroll
    for (int co = 0; co < 4; co++) {
        float4 r;
        r.x = fmaxf(acc[co][0], 0.f); r.y = fmaxf(acc[co][1], 0.f);
        r.z = fmaxf(acc[co][2], 0.f); r.w = fmaxf(acc[co][3], 0.f);
        *(float4*)&out[(long long)((b*4+co)*8+d)*4096 + h*64 + 4*wg] = r;
    }
}

// ========================= conv2 =============================
// h1 (16,4,8,64,64) -> h2 (16,8,4,32,32), k4 s2 p1, relu
// thread: 2 consecutive wo, 8 co. threads = 16*4*32*16 = 32768
__global__ __launch_bounds__(128) void conv2_kernel(
    const float* __restrict__ in, const float* __restrict__ w,
    const float* __restrict__ bias, float* __restrict__ out)
{
    __shared__ float sw[2048];   // [ci4][kd4][kh4][kw4][co8]
    __shared__ float sb[8];
    for (int i = threadIdx.x; i < 2048; i += blockDim.x) {
        int co = i & 7, kw = (i >> 3) & 3, kh = (i >> 5) & 3, kd = (i >> 7) & 3, ci = i >> 9;
        sw[i] = w[(((co*4+ci)*4+kd)*4+kh)*4+kw];
    }
    if (threadIdx.x < 8) sb[threadIdx.x] = bias[threadIdx.x];
    __syncthreads();

    int idx = blockIdx.x * blockDim.x + threadIdx.x;
    int wg = idx & 15;
    int h  = (idx >> 4) & 31;
    int d  = (idx >> 9) & 3;
    int b  = idx >> 11;

    float acc[8][2];
    #pragma unroll
    for (int co = 0; co < 8; co++) { acc[co][0] = sb[co]; acc[co][1] = sb[co]; }

    int iwb = 4*wg - 1;
    #pragma unroll
    for (int ci = 0; ci < 4; ci++) {
        const float* inc = in + (long long)((b*4+ci)*8) * 4096;
        #pragma unroll
        for (int kd = 0; kd < 4; kd++) {
            int id = 2*d - 1 + kd;
            if (id < 0 || id >= 8) continue;
            #pragma unroll
            for (int kh = 0; kh < 4; kh++) {
                int ih = 2*h - 1 + kh;
                if (ih < 0 || ih >= 64) continue;
                const float* row = inc + id*4096 + ih*64;
                float v[6];
                #pragma unroll
                for (int m = 0; m < 6; m++) {
                    int iw = iwb + m;
                    v[m] = (iw >= 0 && iw < 64) ? row[iw] : 0.f;
                }
                const float4* w4 = (const float4*)&sw[((ci*4+kd)*4+kh)*32];
                #pragma unroll
                for (int kw = 0; kw < 4; kw++) {
                    float4 w0 = w4[kw*2], w1 = w4[kw*2+1];
                    #pragma unroll
                    for (int j = 0; j < 2; j++) {
                        float vv = v[2*j+kw];
                        acc[0][j] = fmaf(vv, w0.x, acc[0][j]);
                        acc[1][j] = fmaf(vv, w0.y, acc[1][j]);
                        acc[2][j] = fmaf(vv, w0.z, acc[2][j]);
                        acc[3][j] = fmaf(vv, w0.w, acc[3][j]);
                        acc[4][j] = fmaf(vv, w1.x, acc[4][j]);
                        acc[5][j] = fmaf(vv, w1.y, acc[5][j]);
                        acc[6][j] = fmaf(vv, w1.z, acc[6][j]);
                        acc[7][j] = fmaf(vv, w1.w, acc[7][j]);
                    }
                }
            }
        }
    }
    #pragma unroll
    for (int co = 0; co < 8; co++) {
        float2 r;
        r.x = fmaxf(acc[co][0], 0.f); r.y = fmaxf(acc[co][1], 0.f);
        *(float2*)&out[(long long)((b*8+co)*4+d)*1024 + h*32 + 2*wg] = r;
    }
}

// ========================= conv3 =============================
// h2 (16,8,4,32,32) -> z (16,16,4,32,32), k3 s1 p1, clip[0,6]
// thread: 4 consecutive wo, 8 of 16 co. threads = 16*2*4*32*8 = 32768
__global__ __launch_bounds__(128) void conv3_kernel(
    const float* __restrict__ in, const float* __restrict__ w,
    const float* __restrict__ bias, float* __restrict__ out)
{
    __shared__ float sw[3456];   // [ci8][kd3][kh3][kw3][co16]
    __shared__ float sb[16];
    for (int i = threadIdx.x; i < 3456; i += blockDim.x) {
        int co = i & 15;
        int r = i >> 4;
        int kw = r % 3, kh = (r/3) % 3, kd = (r/9) % 3, ci = r / 27;
        sw[i] = w[(((co*8+ci)*3+kd)*3+kh)*3+kw];
    }
    if (threadIdx.x < 16) sb[threadIdx.x] = bias[threadIdx.x];
    __syncthreads();

    int idx = blockIdx.x * blockDim.x + threadIdx.x;
    int wg   = idx & 7;
    int h    = (idx >> 3) & 31;
    int d    = (idx >> 8) & 3;
    int half = (idx >> 10) & 1;
    int b    = idx >> 11;

    float acc[8][4];
    #pragma unroll
    for (int co = 0; co < 8; co++) {
        float bv = sb[half*8+co];
        #pragma unroll
        for (int j = 0; j < 4; j++) acc[co][j] = bv;
    }

    int iwb = 4*wg - 1;
    #pragma unroll
    for (int ci = 0; ci < 8; ci++) {
        const float* inc = in + (long long)((b*8+ci)*4) * 1024;
        #pragma unroll
        for (int kd = 0; kd < 3; kd++) {
            int id = d - 1 + kd;
            if (id < 0 || id >= 4) continue;
            #pragma unroll
            for (int kh = 0; kh < 3; kh++) {
                int ih = h - 1 + kh;
                if (ih < 0 || ih >= 32) continue;
                const float* row = inc + id*1024 + ih*32;
                float v[6];
                #pragma unroll
                for (int m = 0; m < 6; m++) {
                    int iw = iwb + m;
                    v[m] = (iw >= 0 && iw < 32) ? row[iw] : 0.f;
                }
                const float4* w4 = (const float4*)&sw[((ci*3+kd)*3+kh)*48 + half*8];
                #pragma unroll
                for (int kw = 0; kw < 3; kw++) {
                    float4 w0 = w4[kw*4], w1 = w4[kw*4+1];
                    #pragma unroll
                    for (int j = 0; j < 4; j++) {
                        float vv = v[j+kw];
                        acc[0][j] = fmaf(vv, w0.x, acc[0][j]);
                        acc[1][j] = fmaf(vv, w0.y, acc[1][j]);
                        acc[2][j] = fmaf(vv, w0.z, acc[2][j]);
                        acc[3][j] = fmaf(vv, w0.w, acc[3][j]);
                        acc[4][j] = fmaf(vv, w1.x, acc[4][j]);
                        acc[5][j] = fmaf(vv, w1.y, acc[5][j]);
                        acc[6][j] = fmaf(vv, w1.z, acc[6][j]);
                        acc[7][j] = fmaf(vv, w1.w, acc[7][j]);
                    }
                }
            }
        }
    }
    #pragma unroll
    for (int co = 0; co < 8; co++) {
        float4 r;
        r.x = fminf(fmaxf(acc[co][0], 0.f), 6.f);
        r.y = fminf(fmaxf(acc[co][1], 0.f), 6.f);
        r.z = fminf(fmaxf(acc[co][2], 0.f), 6.f);
        r.w = fminf(fmaxf(acc[co][3], 0.f), 6.f);
        *(float4*)&out[(long long)((b*16+half*8+co)*4+d)*1024 + h*32 + 4*wg] = r;
    }
}

// ========================= VQ =============================
__global__ void vq_kernel(const float* __restrict__ z,
                          const float* __restrict__ emb_in,
                          float* __restrict__ quant,
                          float* __restrict__ codes_out)
{
    __shared__ float se[NCODE * ZC];
    __shared__ float sn[NCODE];
    __shared__ int   sh[NCODE];
    int tid = threadIdx.x;

    for (int i = tid; i < NCODE * ZC; i += blockDim.x) {
        int row = i / ZC;
        float v = __ldg(&emb_in[i]);
        if (row == 0) v = 0.f;
        if (row == 1) v = 6.f;
        se[i] = v;
    }
    if (tid < NCODE) sh[tid] = 0;
    __syncthreads();
    if (tid < NCODE) {
        float s = 0.f;
        for (int c = 0; c < ZC; c++) { float v = se[tid * ZC + c]; s += v * v; }
        sn[tid] = s;
    }
    __syncthreads();

    int p = blockIdx.x * blockDim.x + tid;
    int b = p >> 12;
    int s = p & 4095;
    const float* zb = z + (long long)(b * ZC) * 4096 + s;

    float f[ZC];
    float fn = 0.f;
    #pragma unroll
    for (int c = 0; c < ZC; c++) { f[c] = zb[(long long)c * 4096]; fn += f[c] * f[c]; }

    int best = 0; float bestd = INFINITY;
    for (int e = 0; e < NCODE; e++) {
        float dot = 0.f;
        #pragma unroll
        for (int c = 0; c < ZC; c++) dot += f[c] * se[e * ZC + c];
        float d = fn - 2.f * dot + sn[e];
        if (d < bestd) { bestd = d; best = e; }
    }

    codes_out[p] = (float)best;
    float* qb = quant + (long long)(b * ZC) * 4096 + s;
    float diff2 = 0.f;
    #pragma unroll
    for (int c = 0; c < ZC; c++) {
        float e = se[best * ZC + c];
        qb[(long long)c * 4096] = e;
        float d = e - f[c];
        diff2 += d * d;
    }

    atomicAdd(&sh[best], 1);
    #pragma unroll
    for (int o = 16; o > 0; o >>= 1) diff2 += __shfl_down_sync(0xffffffff, diff2, o);
    if ((tid & 31) == 0) atomicAdd(&g_sqsum, diff2);
    __syncthreads();
    if (tid < NCODE) atomicAdd(&g_hist[tid], sh[tid]);
}

__global__ void finalize_kernel(const float* __restrict__ cluster_size,
                                float* __restrict__ out)
{
    if (threadIdx.x == 0 && blockIdx.x == 0) {
        float invN = 1.f / (float)NPOS;
        float ent = 0.f;
        int used = 0;
        for (int i = 0; i < NCODE; i++) {
            float p = (float)g_hist[i] * invN;
            ent += p * logf(p + 1e-10f);
            if (__ldg(&cluster_size[i]) > 1e-5f) used++;
        }
        out[OUT_ELEMS] = 0.25f * g_sqsum / (float)(NPOS * ZC);
        out[OUT_ELEMS + 1 + NPOS] = expf(-ent);
        out[OUT_ELEMS + 2 + NPOS] = (float)used / (float)NCODE;
    }
}

// ========================= deconv1 =============================
// q (16,16,4,32,32) -> d1 (16,8,8,64,64), k4 s2 p1, relu
// thread: 4 same-parity wo, 8 co. threads = 16*8*64*8*2 = 131072
__global__ __launch_bounds__(256) void deconv1_kernel(
    const float* __restrict__ in, const float* __restrict__ w,
    const float* __restrict__ bias, float* __restrict__ out)
{
    __shared__ float sw[8192];   // [ci16][kd4][kh4][kw4][co8]
    __shared__ float sb[8];
    for (int i = threadIdx.x; i < 8192; i += blockDim.x) {
        int co = i & 7, kw = (i >> 3) & 3, kh = (i >> 5) & 3, kd = (i >> 7) & 3, ci = i >> 9;
        sw[i] = w[(((ci*8+co)*4+kd)*4+kh)*4+kw];
    }
    if (threadIdx.x < 8) sb[threadIdx.x] = bias[threadIdx.x];
    __syncthreads();
    const float4* sw4 = (const float4*)sw;

    int idx = blockIdx.x * blockDim.x + threadIdx.x;
    int par = idx & 1;
    int wg  = (idx >> 1) & 7;
    int ho  = (idx >> 4) & 63;
    int dd  = (idx >> 10) & 7;
    int b   = idx >> 13;

    int wbase = 8*wg + par;
    int iwb = (wbase + 1) >> 1;
    int kwa = (wbase + 1) & 1;

    int ida = (dd + 1) >> 1, kda = (dd + 1) & 1;
    int iha = (ho + 1) >> 1, kha = (ho + 1) & 1;

    float acc[8][4];
    #pragma unroll
    for (int co = 0; co < 8; co++) {
        float bv = sb[co];
        #pragma unroll
        for (int j = 0; j < 4; j++) acc[co][j] = bv;
    }

    #pragma unroll
    for (int dt = 0; dt < 2; dt++) {
        int id = ida - dt, kd = kda + 2*dt;
        if (id < 0 || id >= 4) continue;
        #pragma unroll
        for (int ht = 0; ht < 2; ht++) {
            int ih = iha - ht, kh = kha + 2*ht;
            if (ih < 0 || ih >= 32) continue;
            #pragma unroll
            for (int ci = 0; ci < 16; ci++) {
                const float* row = in + (long long)((b*16+ci)*4+id)*1024 + ih*32;
                float v[5];
                #pragma unroll
                for (int m = 0; m < 5; m++) {
                    int iw = iwb - 1 + m;
                    v[m] = (iw >= 0 && iw < 32) ? row[iw] : 0.f;
                }
                #pragma unroll
                for (int kwt = 0; kwt < 2; kwt++) {
                    int kw = kwa + 2*kwt;
                    int base = ((ci*4+kd)*4+kh)*8 + kw*2;
                    float4 w0 = sw4[base], w1 = sw4[base+1];
                    #pragma unroll
                    for (int j = 0; j < 4; j++) {
                        float vv = v[j + 1 - kwt];
                        acc[0][j] = fmaf(vv, w0.x, acc[0][j]);
                        acc[1][j] = fmaf(vv, w0.y, acc[1][j]);
                        acc[2][j] = fmaf(vv, w0.z, acc[2][j]);
                        acc[3][j] = fmaf(vv, w0.w, acc[3][j]);
                        acc[4][j] = fmaf(vv, w1.x, acc[4][j]);
                        acc[5][j] = fmaf(vv, w1.y, acc[5][j]);
                        acc[6][j] = fmaf(vv, w1.z, acc[6][j]);
                        acc[7][j] = fmaf(vv, w1.w, acc[7][j]);
                    }
                }
            }
        }
    }
    #pragma unroll
    for (int co = 0; co < 8; co++) {
        float* ob = out + (long long)((b*8+co)*8+dd)*4096 + ho*64 + wbase;
        #pragma unroll
        for (int j = 0; j < 4; j++) ob[2*j] = fmaxf(acc[co][j], 0.f);
    }
}

// ========================= deconv3 =============================
// d1 (16,8,8,64,64) -> d2 (16,4,16,128,128), k4 s2 p1, relu
// thread: 4 same-parity wo, 4 co. threads = 16*16*128*16*2 = 1048576
__global__ __launch_bounds__(256) void deconv3_kernel(
    const float* __restrict__ in, const float* __restrict__ w,
    const float* __restrict__ bias, float* __restrict__ out)
{
    __shared__ float sw[2048];   // [ci8][kd4][kh4][kw4][co4]
    __shared__ float sb[4];
    for (int i = threadIdx.x; i < 2048; i += blockDim.x) {
        int co = i & 3, kw = (i >> 2) & 3, kh = (i >> 4) & 3, kd = (i >> 6) & 3, ci = i >> 8;
        sw[i] = w[(((ci*4+co)*4+kd)*4+kh)*4+kw];
    }
    if (threadIdx.x < 4) sb[threadIdx.x] = bias[threadIdx.x];
    __syncthreads();
    const float4* sw4 = (const float4*)sw;

    int idx = blockIdx.x * blockDim.x + threadIdx.x;
    int par = idx & 1;
    int wg  = (idx >> 1) & 15;
    int ho  = (idx >> 5) & 127;
    int dd  = (idx >> 12) & 15;
    int b   = idx >> 16;

    int wbase = 8*wg + par;
    int iwb = (wbase + 1) >> 1;
    int kwa = (wbase + 1) & 1;

    int ida = (dd + 1) >> 1, kda = (dd + 1) & 1;
    int iha = (ho + 1) >> 1, kha = (ho + 1) & 1;

    float acc[4][4];
    #pragma unroll
    for (int co = 0; co < 4; co++) {
        float bv = sb[co];
        #pragma unroll
        for (int j = 0; j < 4; j++) acc[co][j] = bv;
    }

    #pragma unroll
    for (int dt = 0; dt < 2; dt++) {
        int id = ida - dt, kd = kda + 2*dt;
        if (id < 0 || id >= 8) continue;
        #pragma unroll
        for (int ht = 0; ht < 2; ht++) {
            int ih = iha - ht, kh = kha + 2*ht;
            if (ih < 0 || ih >= 64) continue;
            #pragma unroll
            for (int ci = 0; ci < 8; ci++) {
                const float* row = in + (long long)((b*8+ci)*8+id)*4096 + ih*64;
                float v[5];
                #pragma unroll
                for (int m = 0; m < 5; m++) {
                    int iw = iwb - 1 + m;
                    v[m] = (iw >= 0 && iw < 64) ? row[iw] : 0.f;
                }
                #pragma unroll
                for (int kwt = 0; kwt < 2; kwt++) {
                    int kw = kwa + 2*kwt;
                    float4 wv = sw4[((ci*4+kd)*4+kh)*4 + kw];
                    #pragma unroll
                    for (int j = 0; j < 4; j++) {
                        float vv = v[j + 1 - kwt];
                        acc[0][j] = fmaf(vv, wv.x, acc[0][j]);
                        acc[1][j] = fmaf(vv, wv.y, acc[1][j]);
                        acc[2][j] = fmaf(vv, wv.z, acc[2][j]);
                        acc[3][j] = fmaf(vv, wv.w, acc[3][j]);
                    }
                }
            }
        }
    }
    #pragma unroll
    for (int co = 0; co < 4; co++) {
        float* ob = out + (long long)((b*4+co)*16+dd)*16384 + ho*128 + wbase;
        #pragma unroll
        for (int j = 0; j < 4; j++) ob[2*j] = fmaxf(acc[co][j], 0.f);
    }
}

// ========================= deconv4 =============================
// d2 (16,4,16,128,128) -> out (16,3,16,128,128), k3 s1 p1, linear
// deconv k3 s1 p1: out[o] += in[o+1-k] * w[k]
// thread: 4 consecutive wo, 3 co. threads = 16*16*128*32 = 1048576
__global__ __launch_bounds__(256) void deconv4_kernel(
    const float* __restrict__ in, const float* __restrict__ w,
    const float* __restrict__ bias, float* __restrict__ out)
{
    __shared__ float sw[432];   // [ci4][kd3][kh3][kw3][co4pad]
    __shared__ float sb[3];
    for (int i = threadIdx.x; i < 432; i += blockDim.x) {
        int co = i & 3;
        int r = i >> 2;
        int kw = r % 3, kh = (r/3) % 3, kd = (r/9) % 3, ci = r / 27;
        sw[i] = (co < 3) ? w[(((ci*3+co)*3+kd)*3+kh)*3+kw] : 0.f;
    }
    if (threadIdx.x < 3) sb[threadIdx.x] = bias[threadIdx.x];
    __syncthreads();
    const float4* sw4 = (const float4*)sw;

    int idx = blockIdx.x * blockDim.x + threadIdx.x;
    int wg = idx & 31;
    int ho = (idx >> 5) & 127;
    int dd = (idx >> 12) & 15;
    int b  = idx >> 16;

    float acc[3][4];
    #pragma unroll
    for (int co = 0; co < 3; co++) {
        float bv = sb[co];
        #pragma unroll
        for (int j = 0; j < 4; j++) acc[co][j] = bv;
    }

    int iwb = 4*wg - 1;
    #pragma unroll
    for (int ci = 0; ci < 4; ci++) {
        const float* inc = in + (long long)((b*4+ci)*16) * 16384;
        #pragma unroll
        for (int kd = 0; kd < 3; kd++) {
            int id = dd + 1 - kd;
            if (id < 0 || id >= 16) continue;
            #pragma unroll
            for (int kh = 0; kh < 3; kh++) {
                int ih = ho + 1 - kh;
                if (ih < 0 || ih >= 128) continue;
                const float* row = inc + id*16384 + ih*128;
                float v[6];
                #pragma unroll
                for (int m = 0; m < 6; m++) {
                    int iw = iwb + m;
                    v[m] = (iw >= 0 && iw < 128) ? row[iw] : 0.f;
                }
                #pragma unroll
                for (int kw = 0; kw < 3; kw++) {
                    float4 wv = sw4[((ci*3+kd)*3+kh)*3 + kw];
                    #pragma unroll
                    for (int j = 0; j < 4; j++) {
                        float vv = v[j + 2 - kw];
                        acc[0][j] = fmaf(vv, wv.x, acc[0][j]);
                        acc[1][j] = fmaf(vv, wv.y, acc[1][j]);
                        acc[2][j] = fmaf(vv, wv.z, acc[2][j]);
                    }
                }
            }
        }
    }
    #pragma unroll
    for (int co = 0; co < 3; co++) {
        float4 r;
        r.x = acc[co][0]; r.y = acc[co][1]; r.z = acc[co][2]; r.w = acc[co][3];
        *(float4*)&out[(long long)((b*3+co)*16+dd)*16384 + ho*128 + 4*wg] = r;
    }
}

// ---------------------------------------------------------------------------
extern "C" void kernel_launch(void* const* d_in, const int* in_sizes, int n_in,
                              void* d_out, int out_size)
{
    const float* x       = (const float*)d_in[0];
    const float* enc_w1  = (const float*)d_in[2];
    const float* enc_b1  = (const float*)d_in[3];
    const float* enc_w2  = (const float*)d_in[4];
    const float* enc_b2  = (const float*)d_in[5];
    const float* enc_w4  = (const float*)d_in[6];
    const float* enc_b4  = (const float*)d_in[7];
    const float* dec_w1  = (const float*)d_in[8];
    const float* dec_b1  = (const float*)d_in[9];
    const float* dec_w3  = (const float*)d_in[10];
    const float* dec_b3  = (const float*)d_in[11];
    const float* dec_w4  = (const float*)d_in[12];
    const float* dec_b4  = (const float*)d_in[13];
    const float* emb     = (const float*)d_in[14];
    const float* clsz    = (const float*)d_in[15];
    float* out = (float*)d_out;

    float *h1, *h2, *z, *q, *d1, *d2;
    cudaGetSymbolAddress((void**)&h1, g_h1);
    cudaGetSymbolAddress((void**)&h2, g_h2);
    cudaGetSymbolAddress((void**)&z,  g_z);
    cudaGetSymbolAddress((void**)&q,  g_q);
    cudaGetSymbolAddress((void**)&d1, g_d1);
    cudaGetSymbolAddress((void**)&d2, g_d2);

    zero_acc_kernel<<<1, 64>>>();

    conv1_kernel<<<131072/256, 256>>>(x, enc_w1, enc_b1, h1);
    conv2_kernel<<<32768/128, 128>>>(h1, enc_w2, enc_b2, h2);
    conv3_kernel<<<32768/128, 128>>>(h2, enc_w4, enc_b4, z);

    vq_kernel<<<NPOS/256, 256>>>(z, emb, q, out + OUT_ELEMS + 1);
    finalize_kernel<<<1, 32>>>(clsz, out);

    deconv1_kernel<<<131072/256, 256>>>(q, dec_w1, dec_b1, d1);
    deconv3_kernel<<<1048576/256, 256>>>(d1, dec_w3, dec_b3, d2);
    deconv4_kernel<<<1048576/256, 256>>>(d2, dec_w4, dec_b4, out);
}

// round 3
// speedup vs baseline: 13.1457x; 1.0742x over previous
#include <cuda_runtime.h>
#include <math.h>

// ---------------------------------------------------------------------------
//  x:      (16, 3, 16, 128, 128)
//  h1:     (16, 4,  8,  64,  64)   conv k4 s2 p1 + relu
//  h2:     (16, 8,  4,  32,  32)   conv k4 s2 p1 + relu
//  z:      (16,16,  4,  32,  32)   conv k3 s1 p1 + clip[0,6]
//  quant:  (16,16,  4,  32,  32)
//  d1:     (16, 8,  8,  64,  64)   deconv k4 s2 p1 + relu
//  d2:     (16, 4, 16, 128, 128)   deconv k4 s2 p1 + relu
//  out:    (16, 3, 16, 128, 128)   deconv k3 s1 p1
// ---------------------------------------------------------------------------

#define OUT_ELEMS (16*3*16*128*128)
#define NPOS      (16*4*32*32)
#define ZC        16
#define NCODE     32

typedef unsigned long long u64;

__device__ __forceinline__ u64 pack2(float lo, float hi) {
    u64 r; asm("mov.b64 %0, {%1,%2};" : "=l"(r) : "f"(lo), "f"(hi)); return r;
}
__device__ __forceinline__ void unpack2(u64 v, float& lo, float& hi) {
    asm("mov.b64 {%0,%1}, %2;" : "=f"(lo), "=f"(hi) : "l"(v));
}
// d = a*b + d   (packed 2x fp32 FMA, sm_100+)
__device__ __forceinline__ void fma2(u64& d, u64 a, u64 b) {
    asm("fma.rn.f32x2 %0, %1, %2, %0;" : "+l"(d) : "l"(a), "l"(b));
}

__device__ float g_h1[16*4*8*64*64];
__device__ float g_h2[16*8*4*32*32];
__device__ float g_z [16*16*4*32*32];
__device__ float g_q [16*16*4*32*32];
__device__ float g_d1[16*8*8*64*64];
__device__ float g_d2[16*4*16*128*128];
__device__ float g_sqsum;
__device__ int   g_hist[NCODE];

__global__ void zero_acc_kernel() {
    int t = threadIdx.x;
    if (t == 0) g_sqsum = 0.f;
    if (t < NCODE) g_hist[t] = 0;
}

// ========================= conv1 =============================
// x (16,3,16,128,128) -> h1 (16,4,8,64,64), k4 s2 p1, relu
// thread: 4 consecutive wo, 4 co (2 pairs). threads = 131072
__global__ __launch_bounds__(256) void conv1_kernel(
    const float* __restrict__ x, const float* __restrict__ w,
    const float* __restrict__ bias, float* __restrict__ out)
{
    __shared__ __align__(16) float sw[768];   // [ci3][kd4][kh4][kw4][co4]
    __shared__ float sb[4];
    for (int i = threadIdx.x; i < 768; i += blockDim.x) {
        int co = i & 3, kw = (i >> 2) & 3, kh = (i >> 4) & 3, kd = (i >> 6) & 3, ci = i >> 8;
        sw[i] = w[(((co*3+ci)*4+kd)*4+kh)*4+kw];
    }
    if (threadIdx.x < 4) sb[threadIdx.x] = bias[threadIdx.x];
    __syncthreads();
    const u64* sw8 = (const u64*)sw;

    int idx = blockIdx.x * blockDim.x + threadIdx.x;
    int wg = idx & 15;
    int h  = (idx >> 4) & 63;
    int d  = (idx >> 10) & 7;
    int b  = idx >> 13;

    u64 acc[2][4];   // [co-pair][j]
    #pragma unroll
    for (int p = 0; p < 2; p++) {
        u64 bv = pack2(sb[2*p], sb[2*p+1]);
        #pragma unroll
        for (int j = 0; j < 4; j++) acc[p][j] = bv;
    }

    int iwb = 8*wg - 1;
    for (int ci = 0; ci < 3; ci++) {
        const float* inc = x + (long long)(b*3+ci) * 16 * 16384;
        #pragma unroll
        for (int kd = 0; kd < 4; kd++) {
            int id = 2*d - 1 + kd;
            if (id < 0 || id >= 16) continue;
            #pragma unroll
            for (int kh = 0; kh < 4; kh++) {
                int ih = 2*h - 1 + kh;
                if (ih < 0 || ih >= 128) continue;
                const float* row = inc + id*16384 + ih*128;
                u64 s[10];
                #pragma unroll
                for (int m = 0; m < 10; m++) {
                    int iw = iwb + m;
                    float v = (iw >= 0 && iw < 128) ? row[iw] : 0.f;
                    s[m] = pack2(v, v);
                }
                int base = ((ci*4+kd)*4+kh)*8;   // u64 index
                #pragma unroll
                for (int kw = 0; kw < 4; kw++) {
                    u64 w0 = sw8[base + kw*2], w1 = sw8[base + kw*2 + 1];
                    #pragma unroll
                    for (int j = 0; j < 4; j++) {
                        fma2(acc[0][j], s[2*j+kw], w0);
                        fma2(acc[1][j], s[2*j+kw], w1);
                    }
                }
            }
        }
    }
    #pragma unroll
    for (int p = 0; p < 2; p++) {
        float lo[4], hi[4];
        #pragma unroll
        for (int j = 0; j < 4; j++) unpack2(acc[p][j], lo[j], hi[j]);
        float4 r0, r1;
        r0.x = fmaxf(lo[0],0.f); r0.y = fmaxf(lo[1],0.f); r0.z = fmaxf(lo[2],0.f); r0.w = fmaxf(lo[3],0.f);
        r1.x = fmaxf(hi[0],0.f); r1.y = fmaxf(hi[1],0.f); r1.z = fmaxf(hi[2],0.f); r1.w = fmaxf(hi[3],0.f);
        *(float4*)&out[(long long)((b*4+2*p  )*8+d)*4096 + h*64 + 4*wg] = r0;
        *(float4*)&out[(long long)((b*4+2*p+1)*8+d)*4096 + h*64 + 4*wg] = r1;
    }
}

// ========================= conv2 =============================
// h1 (16,4,8,64,64) -> h2 (16,8,4,32,32), k4 s2 p1, relu
// thread: 1 wo, 4 co (half q). threads = 131072
__global__ __launch_bounds__(256) void conv2_kernel(
    const float* __restrict__ in, const float* __restrict__ w,
    const float* __restrict__ bias, float* __restrict__ out)
{
    __shared__ __align__(16) float sw[2048];   // [ci4][kd4][kh4][kw4][co8]
    __shared__ float sb[8];
    for (int i = threadIdx.x; i < 2048; i += blockDim.x) {
        int co = i & 7, kw = (i >> 3) & 3, kh = (i >> 5) & 3, kd = (i >> 7) & 3, ci = i >> 9;
        sw[i] = w[(((co*4+ci)*4+kd)*4+kh)*4+kw];
    }
    if (threadIdx.x < 8) sb[threadIdx.x] = bias[threadIdx.x];
    __syncthreads();
    const u64* sw8 = (const u64*)sw;

    int idx = blockIdx.x * blockDim.x + threadIdx.x;
    int wo = idx & 31;
    int h  = (idx >> 5) & 31;
    int d  = (idx >> 10) & 3;
    int q  = (idx >> 12) & 1;
    int b  = idx >> 13;

    u64 acc[2];
    acc[0] = pack2(sb[4*q], sb[4*q+1]);
    acc[1] = pack2(sb[4*q+2], sb[4*q+3]);

    int iwb = 2*wo - 1;
    #pragma unroll
    for (int ci = 0; ci < 4; ci++) {
        const float* inc = in + (long long)((b*4+ci)*8) * 4096;
        #pragma unroll
        for (int kd = 0; kd < 4; kd++) {
            int id = 2*d - 1 + kd;
            if (id < 0 || id >= 8) continue;
            #pragma unroll
            for (int kh = 0; kh < 4; kh++) {
                int ih = 2*h - 1 + kh;
                if (ih < 0 || ih >= 64) continue;
                const float* row = inc + id*4096 + ih*64;
                u64 s[4];
                #pragma unroll
                for (int m = 0; m < 4; m++) {
                    int iw = iwb + m;
                    float v = (iw >= 0 && iw < 64) ? row[iw] : 0.f;
                    s[m] = pack2(v, v);
                }
                int base = ((ci*4+kd)*4+kh)*16 + q*2;   // u64 index
                #pragma unroll
                for (int kw = 0; kw < 4; kw++) {
                    fma2(acc[0], s[kw], sw8[base + kw*4]);
                    fma2(acc[1], s[kw], sw8[base + kw*4 + 1]);
                }
            }
        }
    }
    float v0,v1,v2,v3;
    unpack2(acc[0], v0, v1); unpack2(acc[1], v2, v3);
    long long ob = (long long)((b*8+4*q)*4+d)*1024 + h*32 + wo;
    out[ob         ] = fmaxf(v0, 0.f);
    out[ob + 4096LL] = fmaxf(v1, 0.f);
    out[ob + 8192LL] = fmaxf(v2, 0.f);
    out[ob +12288LL] = fmaxf(v3, 0.f);
}

// ========================= conv3 =============================
// h2 (16,8,4,32,32) -> z (16,16,4,32,32), k3 s1 p1, clip[0,6]
// thread: 2 wo, 4 co (quarter q). threads = 131072
__global__ __launch_bounds__(256) void conv3_kernel(
    const float* __restrict__ in, const float* __restrict__ w,
    const float* __restrict__ bias, float* __restrict__ out)
{
    __shared__ __align__(16) float sw[3456];   // [ci8][kd3][kh3][kw3][co16]
    __shared__ float sb[16];
    for (int i = threadIdx.x; i < 3456; i += blockDim.x) {
        int co = i & 15;
        int r = i >> 4;
        int kw = r % 3, kh = (r/3) % 3, kd = (r/9) % 3, ci = r / 27;
        sw[i] = w[(((co*8+ci)*3+kd)*3+kh)*3+kw];
    }
    if (threadIdx.x < 16) sb[threadIdx.x] = bias[threadIdx.x];
    __syncthreads();
    const u64* sw8 = (const u64*)sw;

    int idx = blockIdx.x * blockDim.x + threadIdx.x;
    int wg = idx & 15;          // wo = 2*wg
    int h  = (idx >> 4) & 31;
    int d  = (idx >> 9) & 3;
    int q  = (idx >> 11) & 3;   // co = 4q..4q+3
    int b  = idx >> 13;

    u64 acc[2][2];  // [pair][j]
    #pragma unroll
    for (int p = 0; p < 2; p++) {
        u64 bv = pack2(sb[4*q+2*p], sb[4*q+2*p+1]);
        acc[p][0] = bv; acc[p][1] = bv;
    }

    int iwb = 2*wg - 1;
    #pragma unroll
    for (int ci = 0; ci < 8; ci++) {
        const float* inc = in + (long long)((b*8+ci)*4) * 1024;
        #pragma unroll
        for (int kd = 0; kd < 3; kd++) {
            int id = d - 1 + kd;
            if (id < 0 || id >= 4) continue;
            #pragma unroll
            for (int kh = 0; kh < 3; kh++) {
                int ih = h - 1 + kh;
                if (ih < 0 || ih >= 32) continue;
                const float* row = inc + id*1024 + ih*32;
                u64 s[4];
                #pragma unroll
                for (int m = 0; m < 4; m++) {
                    int iw = iwb + m;
                    float v = (iw >= 0 && iw < 32) ? row[iw] : 0.f;
                    s[m] = pack2(v, v);
                }
                int base = ((ci*3+kd)*3+kh)*24 + q*2;   // u64 index into co16 rows
                #pragma unroll
                for (int kw = 0; kw < 3; kw++) {
                    u64 w0 = sw8[base + kw*8], w1 = sw8[base + kw*8 + 1];
                    #pragma unroll
                    for (int j = 0; j < 2; j++) {
                        fma2(acc[0][j], s[j+kw], w0);
                        fma2(acc[1][j], s[j+kw], w1);
                    }
                }
            }
        }
    }
    #pragma unroll
    for (int p = 0; p < 2; p++) {
        float a0,b0,a1,b1;
        unpack2(acc[p][0], a0, b0);
        unpack2(acc[p][1], a1, b1);
        float2 r0, r1;
        r0.x = fminf(fmaxf(a0,0.f),6.f); r0.y = fminf(fmaxf(a1,0.f),6.f);
        r1.x = fminf(fmaxf(b0,0.f),6.f); r1.y = fminf(fmaxf(b1,0.f),6.f);
        *(float2*)&out[(long long)((b*16+4*q+2*p  )*4+d)*1024 + h*32 + 2*wg] = r0;
        *(float2*)&out[(long long)((b*16+4*q+2*p+1)*4+d)*1024 + h*32 + 2*wg] = r1;
    }
}

// ========================= VQ =============================
__global__ void vq_kernel(const float* __restrict__ z,
                          const float* __restrict__ emb_in,
                          float* __restrict__ quant,
                          float* __restrict__ codes_out)
{
    __shared__ float se[NCODE * ZC];
    __shared__ float sn[NCODE];
    __shared__ int   sh[NCODE];
    int tid = threadIdx.x;

    for (int i = tid; i < NCODE * ZC; i += blockDim.x) {
        int row = i / ZC;
        float v = __ldg(&emb_in[i]);
        if (row == 0) v = 0.f;
        if (row == 1) v = 6.f;
        se[i] = v;
    }
    if (tid < NCODE) sh[tid] = 0;
    __syncthreads();
    if (tid < NCODE) {
        float s = 0.f;
        for (int c = 0; c < ZC; c++) { float v = se[tid * ZC + c]; s += v * v; }
        sn[tid] = s;
    }
    __syncthreads();

    int p = blockIdx.x * blockDim.x + tid;
    int b = p >> 12;
    int s = p & 4095;
    const float* zb = z + (long long)(b * ZC) * 4096 + s;

    float f[ZC];
    float fn = 0.f;
    #pragma unroll
    for (int c = 0; c < ZC; c++) { f[c] = zb[(long long)c * 4096]; fn += f[c] * f[c]; }

    int best = 0; float bestd = INFINITY;
    for (int e = 0; e < NCODE; e++) {
        float dot = 0.f;
        #pragma unroll
        for (int c = 0; c < ZC; c++) dot += f[c] * se[e * ZC + c];
        float d = fn - 2.f * dot + sn[e];
        if (d < bestd) { bestd = d; best = e; }
    }

    codes_out[p] = (float)best;
    float* qb = quant + (long long)(b * ZC) * 4096 + s;
    float diff2 = 0.f;
    #pragma unroll
    for (int c = 0; c < ZC; c++) {
        float e = se[best * ZC + c];
        qb[(long long)c * 4096] = e;
        float d = e - f[c];
        diff2 += d * d;
    }

    atomicAdd(&sh[best], 1);
    #pragma unroll
    for (int o = 16; o > 0; o >>= 1) diff2 += __shfl_down_sync(0xffffffff, diff2, o);
    if ((tid & 31) == 0) atomicAdd(&g_sqsum, diff2);
    __syncthreads();
    if (tid < NCODE) atomicAdd(&g_hist[tid], sh[tid]);
}

__global__ void finalize_kernel(const float* __restrict__ cluster_size,
                                float* __restrict__ out)
{
    if (threadIdx.x == 0 && blockIdx.x == 0) {
        float invN = 1.f / (float)NPOS;
        float ent = 0.f;
        int used = 0;
        for (int i = 0; i < NCODE; i++) {
            float p = (float)g_hist[i] * invN;
            ent += p * logf(p + 1e-10f);
            if (__ldg(&cluster_size[i]) > 1e-5f) used++;
        }
        out[OUT_ELEMS] = 0.25f * g_sqsum / (float)(NPOS * ZC);
        out[OUT_ELEMS + 1 + NPOS] = expf(-ent);
        out[OUT_ELEMS + 2 + NPOS] = (float)used / (float)NCODE;
    }
}

// ========================= deconv1 =============================
// q (16,16,4,32,32) -> d1 (16,8,8,64,64), k4 s2 p1, relu
// thread: 4 CONSECUTIVE wo, 8 co (4 pairs). threads = 131072
// w-tap table (w0 = 4*wg even, a = 2*wg, v[m] = in[a-1+m]):
//  j0: (k1,v1)(k3,v0)  j1: (k0,v2)(k2,v1)  j2: (k1,v2)(k3,v1)  j3: (k0,v3)(k2,v2)
__global__ __launch_bounds__(256) void deconv1_kernel(
    const float* __restrict__ in, const float* __restrict__ w,
    const float* __restrict__ bias, float* __restrict__ out)
{
    __shared__ __align__(16) float sw[8192];   // [ci16][kd4][kh4][kw4][co8]
    __shared__ float sb[8];
    for (int i = threadIdx.x; i < 8192; i += blockDim.x) {
        int co = i & 7, kw = (i >> 3) & 3, kh = (i >> 5) & 3, kd = (i >> 7) & 3, ci = i >> 9;
        sw[i] = w[(((ci*8+co)*4+kd)*4+kh)*4+kw];
    }
    if (threadIdx.x < 8) sb[threadIdx.x] = bias[threadIdx.x];
    __syncthreads();
    const u64* sw8 = (const u64*)sw;

    int idx = blockIdx.x * blockDim.x + threadIdx.x;
    int wg = idx & 15;           // w0 = 4*wg
    int ho = (idx >> 4) & 63;
    int dd = (idx >> 10) & 7;
    int b  = idx >> 13;

    int a   = 2*wg;
    int ida = (dd + 1) >> 1, kda = (dd + 1) & 1;
    int iha = (ho + 1) >> 1, kha = (ho + 1) & 1;

    u64 acc[4][4];   // [co-pair][j]
    #pragma unroll
    for (int p = 0; p < 4; p++) {
        u64 bv = pack2(sb[2*p], sb[2*p+1]);
        #pragma unroll
        for (int j = 0; j < 4; j++) acc[p][j] = bv;
    }

    #pragma unroll
    for (int dt = 0; dt < 2; dt++) {
        int id = ida - dt, kd = kda + 2*dt;
        if (id < 0 || id >= 4) continue;
        #pragma unroll
        for (int ht = 0; ht < 2; ht++) {
            int ih = iha - ht, kh = kha + 2*ht;
            if (ih < 0 || ih >= 32) continue;
            #pragma unroll
            for (int ci = 0; ci < 16; ci++) {
                const float* row = in + (long long)((b*16+ci)*4+id)*1024 + ih*32;
                u64 s[4];
                #pragma unroll
                for (int m = 0; m < 4; m++) {
                    int iw = a - 1 + m;
                    float v = (iw >= 0 && iw < 32) ? row[iw] : 0.f;
                    s[m] = pack2(v, v);
                }
                int base = ((ci*4+kd)*4+kh)*16;   // u64 idx of kw0,pair0
                #pragma unroll
                for (int p = 0; p < 4; p++) {
                    u64 wk0 = sw8[base      + p];
                    u64 wk1 = sw8[base +  4 + p];
                    u64 wk2 = sw8[base +  8 + p];
                    u64 wk3 = sw8[base + 12 + p];
                    fma2(acc[p][0], s[1], wk1); fma2(acc[p][0], s[0], wk3);
                    fma2(acc[p][1], s[2], wk0); fma2(acc[p][1], s[1], wk2);
                    fma2(acc[p][2], s[2], wk1); fma2(acc[p][2], s[1], wk3);
                    fma2(acc[p][3], s[3], wk0); fma2(acc[p][3], s[2], wk2);
                }
            }
        }
    }
    #pragma unroll
    for (int p = 0; p < 4; p++) {
        float lo[4], hi[4];
        #pragma unroll
        for (int j = 0; j < 4; j++) unpack2(acc[p][j], lo[j], hi[j]);
        float4 r0, r1;
        r0.x = fmaxf(lo[0],0.f); r0.y = fmaxf(lo[1],0.f); r0.z = fmaxf(lo[2],0.f); r0.w = fmaxf(lo[3],0.f);
        r1.x = fmaxf(hi[0],0.f); r1.y = fmaxf(hi[1],0.f); r1.z = fmaxf(hi[2],0.f); r1.w = fmaxf(hi[3],0.f);
        *(float4*)&out[(long long)((b*8+2*p  )*8+dd)*4096 + ho*64 + 4*wg] = r0;
        *(float4*)&out[(long long)((b*8+2*p+1)*8+dd)*4096 + ho*64 + 4*wg] = r1;
    }
}

// ========================= deconv3 =============================
// d1 (16,8,8,64,64) -> d2 (16,4,16,128,128), k4 s2 p1, relu
// thread: 4 consecutive wo, 4 co (2 pairs). threads = 1048576
__global__ __launch_bounds__(256) void deconv3_kernel(
    const float* __restrict__ in, const float* __restrict__ w,
    const float* __restrict__ bias, float* __restrict__ out)
{
    __shared__ __align__(16) float sw[2048];   // [ci8][kd4][kh4][kw4][co4]
    __shared__ float sb[4];
    for (int i = threadIdx.x; i < 2048; i += blockDim.x) {
        int co = i & 3, kw = (i >> 2) & 3, kh = (i >> 4) & 3, kd = (i >> 6) & 3, ci = i >> 8;
        sw[i] = w[(((ci*4+co)*4+kd)*4+kh)*4+kw];
    }
    if (threadIdx.x < 4) sb[threadIdx.x] = bias[threadIdx.x];
    __syncthreads();
    const u64* sw8 = (const u64*)sw;

    int idx = blockIdx.x * blockDim.x + threadIdx.x;
    int wg = idx & 31;            // w0 = 4*wg
    int ho = (idx >> 5) & 127;
    int dd = (idx >> 12) & 15;
    int b  = idx >> 16;

    int a   = 2*wg;
    int ida = (dd + 1) >> 1, kda = (dd + 1) & 1;
    int iha = (ho + 1) >> 1, kha = (ho + 1) & 1;

    u64 acc[2][4];
    #pragma unroll
    for (int p = 0; p < 2; p++) {
        u64 bv = pack2(sb[2*p], sb[2*p+1]);
        #pragma unroll
        for (int j = 0; j < 4; j++) acc[p][j] = bv;
    }

    #pragma unroll
    for (int dt = 0; dt < 2; dt++) {
        int id = ida - dt, kd = kda + 2*dt;
        if (id < 0 || id >= 8) continue;
        #pragma unroll
        for (int ht = 0; ht < 2; ht++) {
            int ih = iha - ht, kh = kha + 2*ht;
            if (ih < 0 || ih >= 64) continue;
            #pragma unroll
            for (int ci = 0; ci < 8; ci++) {
                const float* row = in + (long long)((b*8+ci)*8+id)*4096 + ih*64;
                u64 s[4];
                #pragma unroll
                for (int m = 0; m < 4; m++) {
                    int iw = a - 1 + m;
                    float v = (iw >= 0 && iw < 64) ? row[iw] : 0.f;
                    s[m] = pack2(v, v);
                }
                int base = ((ci*4+kd)*4+kh)*8;   // u64 idx kw0,pair0
                #pragma unroll
                for (int p = 0; p < 2; p++) {
                    u64 wk0 = sw8[base     + p];
                    u64 wk1 = sw8[base + 2 + p];
                    u64 wk2 = sw8[base + 4 + p];
                    u64 wk3 = sw8[base + 6 + p];
                    fma2(acc[p][0], s[1], wk1); fma2(acc[p][0], s[0], wk3);
                    fma2(acc[p][1], s[2], wk0); fma2(acc[p][1], s[1], wk2);
                    fma2(acc[p][2], s[2], wk1); fma2(acc[p][2], s[1], wk3);
                    fma2(acc[p][3], s[3], wk0); fma2(acc[p][3], s[2], wk2);
                }
            }
        }
    }
    #pragma unroll
    for (int p = 0; p < 2; p++) {
        float lo[4], hi[4];
        #pragma unroll
        for (int j = 0; j < 4; j++) unpack2(acc[p][j], lo[j], hi[j]);
        float4 r0, r1;
        r0.x = fmaxf(lo[0],0.f); r0.y = fmaxf(lo[1],0.f); r0.z = fmaxf(lo[2],0.f); r0.w = fmaxf(lo[3],0.f);
        r1.x = fmaxf(hi[0],0.f); r1.y = fmaxf(hi[1],0.f); r1.z = fmaxf(hi[2],0.f); r1.w = fmaxf(hi[3],0.f);
        *(float4*)&out[(long long)((b*4+2*p  )*16+dd)*16384 + ho*128 + 4*wg] = r0;
        *(float4*)&out[(long long)((b*4+2*p+1)*16+dd)*16384 + ho*128 + 4*wg] = r1;
    }
}

// ========================= deconv4 =============================
// d2 (16,4,16,128,128) -> out (16,3,16,128,128), k3 s1 p1, linear
// thread: 4 consecutive wo, 4 co (pad, 2 pairs; co3 discarded). threads = 1048576
__global__ __launch_bounds__(256) void deconv4_kernel(
    const float* __restrict__ in, const float* __restrict__ w,
    const float* __restrict__ bias, float* __restrict__ out)
{
    __shared__ __align__(16) float sw[432];   // [ci4][kd3][kh3][kw3][co4pad]
    __shared__ float sb[4];
    for (int i = threadIdx.x; i < 432; i += blockDim.x) {
        int co = i & 3;
        int r = i >> 2;
        int kw = r % 3, kh = (r/3) % 3, kd = (r/9) % 3, ci = r / 27;
        sw[i] = (co < 3) ? w[(((ci*3+co)*3+kd)*3+kh)*3+kw] : 0.f;
    }
    if (threadIdx.x < 4) sb[threadIdx.x] = (threadIdx.x < 3) ? bias[threadIdx.x] : 0.f;
    __syncthreads();
    const u64* sw8 = (const u64*)sw;

    int idx = blockIdx.x * blockDim.x + threadIdx.x;
    int wg = idx & 31;
    int ho = (idx >> 5) & 127;
    int dd = (idx >> 12) & 15;
    int b  = idx >> 16;

    u64 acc[2][4];
    #pragma unroll
    for (int p = 0; p < 2; p++) {
        u64 bv = pack2(sb[2*p], sb[2*p+1]);
        #pragma unroll
        for (int j = 0; j < 4; j++) acc[p][j] = bv;
    }

    int iwb = 4*wg - 1;
    #pragma unroll
    for (int ci = 0; ci < 4; ci++) {
        const float* inc = in + (long long)((b*4+ci)*16) * 16384;
        #pragma unroll
        for (int kd = 0; kd < 3; kd++) {
            int id = dd + 1 - kd;
            if (id < 0 || id >= 16) continue;
            #pragma unroll
            for (int kh = 0; kh < 3; kh++) {
                int ih = ho + 1 - kh;
                if (ih < 0 || ih >= 128) continue;
                const float* row = inc + id*16384 + ih*128;
                u64 s[6];
                #pragma unroll
                for (int m = 0; m < 6; m++) {
                    int iw = iwb + m;
                    float v = (iw >= 0 && iw < 128) ? row[iw] : 0.f;
                    s[m] = pack2(v, v);
                }
                int base = ((ci*3+kd)*3+kh)*6;   // u64 idx kw0,pair0
                #pragma unroll
                for (int kw = 0; kw < 3; kw++) {
                    u64 w0 = sw8[base + kw*2], w1 = sw8[base + kw*2 + 1];
                    #pragma unroll
                    for (int j = 0; j < 4; j++) {
                        fma2(acc[0][j], s[j+2-kw], w0);
                        fma2(acc[1][j], s[j+2-kw], w1);
                    }
                }
            }
        }
    }
    // co0, co1 from pair0; co2 from pair1.lo; pair1.hi discarded
    float lo0[4], hi0[4], lo1[4], hi1[4];
    #pragma unroll
    for (int j = 0; j < 4; j++) { unpack2(acc[0][j], lo0[j], hi0[j]); unpack2(acc[1][j], lo1[j], hi1[j]); }
    float4 r0, r1, r2;
    r0.x=lo0[0]; r0.y=lo0[1]; r0.z=lo0[2]; r0.w=lo0[3];
    r1.x=hi0[0]; r1.y=hi0[1]; r1.z=hi0[2]; r1.w=hi0[3];
    r2.x=lo1[0]; r2.y=lo1[1]; r2.z=lo1[2]; r2.w=lo1[3];
    *(float4*)&out[(long long)((b*3+0)*16+dd)*16384 + ho*128 + 4*wg] = r0;
    *(float4*)&out[(long long)((b*3+1)*16+dd)*16384 + ho*128 + 4*wg] = r1;
    *(float4*)&out[(long long)((b*3+2)*16+dd)*16384 + ho*128 + 4*wg] = r2;
}

// ---------------------------------------------------------------------------
extern "C" void kernel_launch(void* const* d_in, const int* in_sizes, int n_in,
                              void* d_out, int out_size)
{
    const float* x       = (const float*)d_in[0];
    const float* enc_w1  = (const float*)d_in[2];
    const float* enc_b1  = (const float*)d_in[3];
    const float* enc_w2  = (const float*)d_in[4];
    const float* enc_b2  = (const float*)d_in[5];
    const float* enc_w4  = (const float*)d_in[6];
    const float* enc_b4  = (const float*)d_in[7];
    const float* dec_w1  = (const float*)d_in[8];
    const float* dec_b1  = (const float*)d_in[9];
    const float* dec_w3  = (const float*)d_in[10];
    const float* dec_b3  = (const float*)d_in[11];
    const float* dec_w4  = (const float*)d_in[12];
    const float* dec_b4  = (const float*)d_in[13];
    const float* emb     = (const float*)d_in[14];
    const float* clsz    = (const float*)d_in[15];
    float* out = (float*)d_out;

    float *h1, *h2, *z, *q, *d1, *d2;
    cudaGetSymbolAddress((void**)&h1, g_h1);
    cudaGetSymbolAddress((void**)&h2, g_h2);
    cudaGetSymbolAddress((void**)&z,  g_z);
    cudaGetSymbolAddress((void**)&q,  g_q);
    cudaGetSymbolAddress((void**)&d1, g_d1);
    cudaGetSymbolAddress((void**)&d2, g_d2);

    zero_acc_kernel<<<1, 64>>>();

    conv1_kernel<<<512, 256>>>(x, enc_w1, enc_b1, h1);
    conv2_kernel<<<512, 256>>>(h1, enc_w2, enc_b2, h2);
    conv3_kernel<<<512, 256>>>(h2, enc_w4, enc_b4, z);

    vq_kernel<<<NPOS/256, 256>>>(z, emb, q, out + OUT_ELEMS + 1);
    finalize_kernel<<<1, 32>>>(clsz, out);

    deconv1_kernel<<<512, 256>>>(q, dec_w1, dec_b1, d1);
    deconv3_kernel<<<4096, 256>>>(d1, dec_w3, dec_b3, d2);
    deconv4_kernel<<<4096, 256>>>(d2, dec_w4, dec_b4, out);
}